// round 15
// baseline (speedup 1.0000x reference)
#include <cuda_runtime.h>
#include <cuda_fp16.h>

// Problem constants
#define NN    50000
#define EE    800000
#define ROWH  128       // fp16 T-table stride in halves: col 2l at halves [8l..8l+8), col 2l+1 at [64+8l..)
#define MT    3125      // 16-node m-tiles for node prep
#define WSTRIDE 168
#define SSTRIDE 136
#define SLOTCAP (EE + 16 * NN)        // 1.6M padded edge slots (upper bound)
#define TILECAP (SLOTCAP / 16)        // 100000 warp tiles
#define NB1   196                     // ceil(NN/256) scan blocks

// ---------------- scratch (static device memory; no runtime allocation) ----------------
__device__ __half g_TextH[(size_t)NN * ROWH];     // 12.8 MB
__device__ float  g_xb[NN * 16];
__device__ float  g_rootx[NN * 16];
__device__ float  g_agg0[(NN + 1) * 16];          // row NN = dump for pad slots
__device__ float  g_agg1[(NN + 1) * 16];
__device__ float  g_cnt[NN];                      // dst in-degree (float)
__device__ int    g_cnts[NN];                     // src out-degree
__device__ int    g_cursor[NN];
__device__ int    g_off[NN + 2];                  // padded slot offsets; g_off[NN] = total slots
__device__ int    g_bsum[NB1];
__device__ int    g_bpre[NB1];
__device__ __half g_eaS[(size_t)SLOTCAP * 8];     // slot-ordered fp16 edge attrs (pads stay 0 from BSS)
__device__ int2   g_sdS[SLOTCAP];                 // {src, dst} per slot; pads get {0, NN}
__device__ int    g_is64;

// ---------------- helpers ----------------
__device__ __forceinline__ unsigned tf32_of(float f) {
    unsigned r;
    asm("cvt.rna.tf32.f32 %0, %1;" : "=r"(r) : "f"(f));
    return r;
}

__device__ __forceinline__ void mma_tf32(float& c0, float& c1, float& c2, float& c3,
                                         unsigned a0, unsigned a1, unsigned a2, unsigned a3,
                                         unsigned b0, unsigned b1) {
    asm("mma.sync.aligned.m16n8k8.row.col.f32.tf32.tf32.f32 "
        "{%0,%1,%2,%3},{%4,%5,%6,%7},{%8,%9},{%0,%1,%2,%3};"
        : "+f"(c0), "+f"(c1), "+f"(c2), "+f"(c3)
        : "r"(a0), "r"(a1), "r"(a2), "r"(a3), "r"(b0), "r"(b1));
}

__device__ __forceinline__ void mma_f16(float& c0, float& c1, float& c2, float& c3,
                                        unsigned a0, unsigned a1, unsigned b0) {
    asm("mma.sync.aligned.m16n8k8.row.col.f32.f16.f16.f32 "
        "{%0,%1,%2,%3},{%4,%5},{%6},{%0,%1,%2,%3};"
        : "+f"(c0), "+f"(c1), "+f"(c2), "+f"(c3)
        : "r"(a0), "r"(a1), "r"(b0));
}

__device__ __forceinline__ void red2(float* p, float a, float b) {
    asm volatile("red.global.add.v2.f32 [%0], {%1, %2};"
                 :: "l"(p), "f"(a), "f"(b) : "memory");
}

__device__ __forceinline__ int ld_src(const void* ei, int e) {
    return g_is64 ? (int)((const long long*)ei)[e] : ((const int*)ei)[e];
}
__device__ __forceinline__ int ld_dst(const void* ei, int e) {
    return g_is64 ? (int)((const long long*)ei)[EE + e] : ((const int*)ei)[EE + e];
}

// ---------------- build kernels ----------------

// Zero counters; block0/warp0 probes dtype (int64 vs JAX-x64-disabled int32).
__global__ void __launch_bounds__(256) zero_detect_kernel(const void* ei) {
    if (blockIdx.x == 0 && threadIdx.x < 32) {
        const unsigned long long* p = (const unsigned long long*)ei;
        int t = threadIdx.x;
        bool bad = (p[t] >= (unsigned long long)NN) ||
                   (p[t + 32] >= (unsigned long long)NN);
        unsigned m = __ballot_sync(0xffffffffu, bad);
        if (t == 0) g_is64 = (m == 0) ? 1 : 0;
    }
    int idx = blockIdx.x * blockDim.x + threadIdx.x;
    int stride = gridDim.x * blockDim.x;
    for (int i = idx; i < NN; i += stride) {
        g_cnts[i] = 0;
        g_cursor[i] = 0;
        g_cnt[i] = 0.f;
    }
}

// src out-degree + dst in-degree histograms.
__global__ void __launch_bounds__(256) hist_kernel(const void* __restrict__ ei) {
    int e = blockIdx.x * blockDim.x + threadIdx.x;
    if (e >= EE) return;
    int src = ld_src(ei, e);
    int dst = ld_dst(ei, e);
    if ((unsigned)src < NN) atomicAdd(&g_cnts[src], 1);
    if ((unsigned)dst < NN) atomicAdd(&g_cnt[dst], 1.0f);
}

// Scan phase 1: per-block sums of 16-padded counts.
__global__ void __launch_bounds__(256) scan1_kernel() {
    __shared__ int sh[256];
    int n = blockIdx.x * 256 + threadIdx.x;
    int pc = (n < NN) ? ((g_cnts[n] + 15) & ~15) : 0;
    sh[threadIdx.x] = pc;
    __syncthreads();
    for (int d = 128; d > 0; d >>= 1) {
        if (threadIdx.x < d) sh[threadIdx.x] += sh[threadIdx.x + d];
        __syncthreads();
    }
    if (threadIdx.x == 0) g_bsum[blockIdx.x] = sh[0];
}

// Scan phase 2: scan NB1 block sums; total -> g_off[NN].
__global__ void __launch_bounds__(256) scan2_kernel() {
    __shared__ int sh[256];
    int t = threadIdx.x;
    int v = (t < NB1) ? g_bsum[t] : 0;
    int incl = v;
    for (int d = 1; d < 256; d <<= 1) {
        sh[t] = incl;
        __syncthreads();
        if (t >= d) incl += sh[t - d];
        __syncthreads();
    }
    if (t < NB1) g_bpre[t] = incl - v;
    if (t == NB1 - 1) g_off[NN] = incl;
}

// Scan phase 3: final padded offsets; fill pad slots' {src,dst} with {0, NN}.
__global__ void __launch_bounds__(256) scan3_kernel() {
    __shared__ int sh[256];
    int t = threadIdx.x;
    int n = blockIdx.x * 256 + t;
    int cnt = (n < NN) ? g_cnts[n] : 0;
    int pc = (cnt + 15) & ~15;
    int incl = pc;
    for (int d = 1; d < 256; d <<= 1) {
        sh[t] = incl;
        __syncthreads();
        if (t >= d) incl += sh[t - d];
        __syncthreads();
    }
    if (n < NN) {
        int off = g_bpre[blockIdx.x] + incl - pc;
        g_off[n] = off;
        for (int j = cnt; j < pc; j++)
            g_sdS[off + j] = make_int2(0, NN);
    }
}

// Scatter edges into src-grouped padded slots; ea converted to fp16 inline.
__global__ void __launch_bounds__(256) scatter_kernel(const void* __restrict__ ei,
                                                      const float* __restrict__ ea) {
    int e = blockIdx.x * blockDim.x + threadIdx.x;
    if (e >= EE) return;
    int src = ld_src(ei, e);
    int dst = ld_dst(ei, e);
    if ((unsigned)src >= NN) return;
    if ((unsigned)dst >= NN) dst = NN;       // dump
    int p = g_off[src] + atomicAdd(&g_cursor[src], 1);
    g_sdS[p] = make_int2(src, dst);
    const float4* ep = (const float4*)(ea + (size_t)e * 8);
    float4 u = ep[0], v = ep[1];
    __half2 h0 = __floats2half2_rn(u.x, u.y);
    __half2 h1 = __floats2half2_rn(u.z, u.w);
    __half2 h2 = __floats2half2_rn(v.x, v.y);
    __half2 h3 = __floats2half2_rn(v.z, v.w);
    unsigned w0 = *(unsigned*)&h0;
    unsigned w1 = *(unsigned*)&h1;
    unsigned w2 = *(unsigned*)&h2;
    unsigned w3 = *(unsigned*)&h3;
    *(uint4*)(g_eaS + (size_t)p * 8) = make_uint4(w0, w1, w2, w3);
}

// ---------------- node prep (unchanged tf32 MMA core from R12/R14) ----------------
// mode 0: input = x; zeroes agg0 (incl dump row).
// mode 1: input = relu(agg0/max(cnt,1)+rootx) inline; zeroes agg1.
__global__ void __launch_bounds__(256)
node_prep_kernel(const float* __restrict__ xin,
                 const float* __restrict__ nw,
                 const float* __restrict__ nb,
                 const float* __restrict__ rt,
                 const float* __restrict__ bs,
                 int mode) {
    __shared__ unsigned Wt[16 * WSTRIDE];
    __shared__ float    Bs[16];
    __shared__ __half   stage[8][16 * SSTRIDE];

    {
        int idx = blockIdx.x * blockDim.x + threadIdx.x;
        int stride = gridDim.x * blockDim.x;
        float4 z4 = make_float4(0.f, 0.f, 0.f, 0.f);
        float4* aggv = (float4*)(mode == 0 ? g_agg0 : g_agg1);
        for (int i = idx; i < (NN + 1) * 4; i += stride) aggv[i] = z4;
    }

    for (int t = threadIdx.x; t < 16 * 160; t += blockDim.x) {
        int i = t / 160, j = t % 160;
        float w;
        if (j < 128) {
            int d = j >> 4, o = j & 15;
            w = nw[d * 256 + i * 16 + o];
        } else if (j < 144) {
            w = nb[i * 16 + (j - 128)];
        } else {
            w = rt[i * 16 + (j - 144)];
        }
        Wt[i * WSTRIDE + j] = tf32_of(w);
    }
    if (threadIdx.x < 16) Bs[threadIdx.x] = bs[threadIdx.x];
    __syncthreads();

    int wid = threadIdx.x >> 5;
    int lane = threadIdx.x & 31;
    int g = lane >> 2;
    int t4 = lane & 3;

    int m = blockIdx.x * 8 + wid;
    if (m >= MT) return;
    int base = m * 16;

    unsigned A[2][4];
    if (mode == 0) {
        const float* x0 = xin + (size_t)(base + g) * 16;
        const float* x1 = xin + (size_t)(base + g + 8) * 16;
#pragma unroll
        for (int kh = 0; kh < 2; kh++) {
            A[kh][0] = tf32_of(x0[kh * 8 + t4]);
            A[kh][1] = tf32_of(x1[kh * 8 + t4]);
            A[kh][2] = tf32_of(x0[kh * 8 + t4 + 4]);
            A[kh][3] = tf32_of(x1[kh * 8 + t4 + 4]);
        }
    } else {
        int r0 = base + g, r1 = base + g + 8;
        float inv0 = 1.f / fmaxf(g_cnt[r0], 1.f);
        float inv1 = 1.f / fmaxf(g_cnt[r1], 1.f);
        const float* a0p = g_agg0 + (size_t)r0 * 16;
        const float* a1p = g_agg0 + (size_t)r1 * 16;
        const float* x0p = g_rootx + (size_t)r0 * 16;
        const float* x1p = g_rootx + (size_t)r1 * 16;
#pragma unroll
        for (int kh = 0; kh < 2; kh++) {
            int k = kh * 8 + t4;
            A[kh][0] = tf32_of(fmaxf(fmaf(a0p[k], inv0, x0p[k]), 0.f));
            A[kh][1] = tf32_of(fmaxf(fmaf(a1p[k], inv1, x1p[k]), 0.f));
            A[kh][2] = tf32_of(fmaxf(fmaf(a0p[k + 4], inv0, x0p[k + 4]), 0.f));
            A[kh][3] = tf32_of(fmaxf(fmaf(a1p[k + 4], inv1, x1p[k + 4]), 0.f));
        }
    }

    __half* st = stage[wid];

#pragma unroll
    for (int nbt = 0; nbt < 20; nbt++) {
        float c0 = 0.f, c1 = 0.f, c2 = 0.f, c3 = 0.f;
#pragma unroll
        for (int kh = 0; kh < 2; kh++) {
            unsigned b0 = Wt[(kh * 8 + t4) * WSTRIDE + nbt * 8 + g];
            unsigned b1 = Wt[(kh * 8 + t4 + 4) * WSTRIDE + nbt * 8 + g];
            mma_tf32(c0, c1, c2, c3, A[kh][0], A[kh][1], A[kh][2], A[kh][3], b0, b1);
        }
        if (nbt < 16) {
            int d = nbt >> 1;
            int o0 = (nbt & 1) * 8 + 2 * t4;
            int idx0 = (o0 >> 1) * 8 + d;
            st[g * SSTRIDE + idx0]            = __float2half_rn(c0);
            st[g * SSTRIDE + idx0 + 64]       = __float2half_rn(c1);
            st[(g + 8) * SSTRIDE + idx0]      = __float2half_rn(c2);
            st[(g + 8) * SSTRIDE + idx0 + 64] = __float2half_rn(c3);
        } else if (nbt < 18) {
            int o0 = (nbt - 16) * 8 + 2 * t4;
            *(float2*)&g_xb[(size_t)(base + g) * 16 + o0]     = make_float2(c0, c1);
            *(float2*)&g_xb[(size_t)(base + g + 8) * 16 + o0] = make_float2(c2, c3);
        } else {
            int o0 = (nbt - 18) * 8 + 2 * t4;
            float b0v = Bs[o0], b1v = Bs[o0 + 1];
            *(float2*)&g_rootx[(size_t)(base + g) * 16 + o0]     = make_float2(c0 + b0v, c1 + b1v);
            *(float2*)&g_rootx[(size_t)(base + g + 8) * 16 + o0] = make_float2(c2 + b0v, c3 + b1v);
        }
    }
    __syncwarp();

    for (int it = lane; it < 256; it += 32) {
        int r = it >> 4;
        int q = it & 15;
        float4 v = *(const float4*)(st + r * SSTRIDE + q * 8);
        *(float4*)((char*)(g_TextH + (size_t)(base + r) * ROWH) + q * 16) = v;
    }
}

// ---------------- edge MMA kernel ----------------
// Warp handles one 16-slot tile (single src): C[16,16] = EA[16,8] @ T_src[8,16]
// via two mma.m16n8k8.f16.f32, then adds xb[src] and red2-scatters to dst rows.
// Pad slots carry ea=0 (BSS) and dst=NN (dump row) -> branch-free.
__global__ void __launch_bounds__(256)
edge_mma_kernel(int layer) {
    int wtile = blockIdx.x * 8 + (threadIdx.x >> 5);
    int tot = g_off[NN];
    if (wtile * 16 >= tot) return;
    int lane = threadIdx.x & 31;
    int g = lane >> 2;
    int t4 = lane & 3;
    int base = wtile * 16;

    int src = g_sdS[base].x;                    // whole warp: same addr (broadcast)

    // A fragments: rows g, g+8 of EA (16 rows x 8 halves = 16B/row)
    const __half* eaRow = g_eaS + (size_t)(base + g) * 8;
    unsigned a0 = *(const unsigned*)(eaRow + 2 * t4);
    unsigned a1 = *(const unsigned*)(eaRow + 64 + 2 * t4);   // row g+8

    // B fragments from fp16 T row (o-major permuted): col c at halves
    //   (c even) 8*(c/2)  |  (c odd) 64 + 8*(c/2);  lane takes d = 2t4, 2t4+1.
    const __half* trow = g_TextH + (size_t)src * ROWH;
    int cb0 = ((g & 1) ? 64 + 8 * (g >> 1) : 8 * (g >> 1)) + 2 * t4;
    int c1i = 8 + g;
    int cb1 = ((c1i & 1) ? 64 + 8 * (c1i >> 1) : 8 * (c1i >> 1)) + 2 * t4;
    unsigned b0 = *(const unsigned*)(trow + cb0);
    unsigned b1 = *(const unsigned*)(trow + cb1);

    float c00 = 0.f, c01 = 0.f, c02 = 0.f, c03 = 0.f;
    float c10 = 0.f, c11 = 0.f, c12 = 0.f, c13 = 0.f;
    mma_f16(c00, c01, c02, c03, a0, a1, b0);   // cols 0..7 (ntile0)
    mma_f16(c10, c11, c12, c13, a0, a1, b1);   // cols 8..15 (ntile1)

    float2 xbA = *(const float2*)(g_xb + (size_t)src * 16 + 2 * t4);
    float2 xbB = *(const float2*)(g_xb + (size_t)src * 16 + 8 + 2 * t4);

    int dlo = g_sdS[base + g].y;
    int dhi = g_sdS[base + g + 8].y;

    float* agg = layer ? g_agg1 : g_agg0;
    red2(agg + (size_t)dlo * 16 + 2 * t4,     c00 + xbA.x, c01 + xbA.y);
    red2(agg + (size_t)dlo * 16 + 8 + 2 * t4, c10 + xbB.x, c11 + xbB.y);
    red2(agg + (size_t)dhi * 16 + 2 * t4,     c02 + xbA.x, c03 + xbA.y);
    red2(agg + (size_t)dhi * 16 + 8 + 2 * t4, c12 + xbB.x, c13 + xbB.y);
}

// out[n] = sum_o relu(agg1[n,o]/max(cnt,1) + rootx[n,o]) * head_w[o] + head_b
__global__ void __launch_bounds__(256)
head_kernel(const float* __restrict__ hw,
            const float* __restrict__ hb,
            float* __restrict__ out) {
    int n = blockIdx.x * blockDim.x + threadIdx.x;
    if (n >= NN) return;
    float inv = 1.f / fmaxf(g_cnt[n], 1.f);
    const float4* ag = (const float4*)(g_agg1 + (size_t)n * 16);
    const float4* rx = (const float4*)(g_rootx + (size_t)n * 16);
    float s = hb[0];
#pragma unroll
    for (int q = 0; q < 4; q++) {
        float4 a = ag[q], r = rx[q];
        const float4 w = ((const float4*)hw)[q];
        s = fmaf(fmaxf(fmaf(a.x, inv, r.x), 0.f), w.x, s);
        s = fmaf(fmaxf(fmaf(a.y, inv, r.y), 0.f), w.y, s);
        s = fmaf(fmaxf(fmaf(a.z, inv, r.z), 0.f), w.z, s);
        s = fmaf(fmaxf(fmaf(a.w, inv, r.w), 0.f), w.w, s);
    }
    out[n] = s;
}

// ---------------- launch ----------------
extern "C" void kernel_launch(void* const* d_in, const int* in_sizes, int n_in,
                              void* d_out, int out_size) {
    const float* x     = (const float*)d_in[0];
    const void*  ei    = d_in[1];
    const float* ea    = (const float*)d_in[2];
    const float* nn_w0 = (const float*)d_in[3];
    const float* nn_b0 = (const float*)d_in[4];
    const float* root0 = (const float*)d_in[5];
    const float* bias0 = (const float*)d_in[6];
    const float* nn_w1 = (const float*)d_in[7];
    const float* nn_b1 = (const float*)d_in[8];
    const float* root1 = (const float*)d_in[9];
    const float* bias1 = (const float*)d_in[10];
    const float* headw = (const float*)d_in[11];
    const float* headb = (const float*)d_in[12];
    float* out = (float*)d_out;

    const int TB = 256;
    const int EB = EE / TB;               // 3125, exact
    const int PB = (MT + 7) / 8;          // 391
    const int MB = TILECAP / 8;           // 12500 blocks, 8 warp-tiles each

    zero_detect_kernel<<<256, TB>>>(ei);
    hist_kernel<<<EB, TB>>>(ei);
    scan1_kernel<<<NB1, TB>>>();
    scan2_kernel<<<1, TB>>>();
    scan3_kernel<<<NB1, TB>>>();
    scatter_kernel<<<EB, TB>>>(ei, ea);
    node_prep_kernel<<<PB, TB>>>(x, nn_w0, nn_b0, root0, bias0, /*mode=*/0);
    edge_mma_kernel<<<MB, TB>>>(/*layer=*/0);
    node_prep_kernel<<<PB, TB>>>(nullptr, nn_w1, nn_b1, root1, bias1, /*mode=*/1);
    edge_mma_kernel<<<MB, TB>>>(/*layer=*/1);
    head_kernel<<<(NN + TB - 1) / TB, TB>>>(headw, headb, out);
}

// round 16
// speedup vs baseline: 14.4460x; 14.4460x over previous
#include <cuda_runtime.h>
#include <cuda_fp16.h>

// Problem constants
#define NN    50000
#define EE    800000
#define ROWH  128       // fp16 T-table stride in halves: col 2l at halves [8l..8l+8), col 2l+1 at [64+8l..)
#define MT    3125      // 16-node m-tiles for node prep
#define WSTRIDE 168
#define SSTRIDE 136
#define SLOTCAP (EE + 16 * NN)        // 1.6M padded edge slots (upper bound)
#define TILECAP (SLOTCAP / 16)        // 100000 warp tiles
#define NB1   196                     // ceil(NN/256) scan blocks

// ---------------- scratch (static device memory; no runtime allocation) ----------------
__device__ __half g_TextH[(size_t)NN * ROWH];     // 12.8 MB
__device__ float  g_xb[NN * 16];
__device__ float  g_rootx[NN * 16];
__device__ float  g_agg0[(NN + 1) * 16];          // row NN unused now (kept for safety)
__device__ float  g_agg1[(NN + 1) * 16];
__device__ float  g_cnt[NN];                      // dst in-degree (float)
__device__ int    g_cnts[NN];                     // src out-degree
__device__ int    g_cursor[NN];
__device__ int    g_off[NN + 2];                  // padded slot offsets; g_off[NN] = total slots
__device__ int    g_bsum[NB1];
__device__ int    g_bpre[NB1];
__device__ __half g_eaS[(size_t)SLOTCAP * 8];     // slot-ordered fp16 edge attrs (pads stay 0 from BSS)
__device__ int2   g_sdS[SLOTCAP];                 // {src, dst} per slot; pads get {0, NN}
__device__ int    g_is64;

// ---------------- helpers ----------------
__device__ __forceinline__ unsigned tf32_of(float f) {
    unsigned r;
    asm("cvt.rna.tf32.f32 %0, %1;" : "=r"(r) : "f"(f));
    return r;
}

__device__ __forceinline__ void mma_tf32(float& c0, float& c1, float& c2, float& c3,
                                         unsigned a0, unsigned a1, unsigned a2, unsigned a3,
                                         unsigned b0, unsigned b1) {
    asm("mma.sync.aligned.m16n8k8.row.col.f32.tf32.tf32.f32 "
        "{%0,%1,%2,%3},{%4,%5,%6,%7},{%8,%9},{%0,%1,%2,%3};"
        : "+f"(c0), "+f"(c1), "+f"(c2), "+f"(c3)
        : "r"(a0), "r"(a1), "r"(a2), "r"(a3), "r"(b0), "r"(b1));
}

__device__ __forceinline__ void mma_f16(float& c0, float& c1, float& c2, float& c3,
                                        unsigned a0, unsigned a1, unsigned b0) {
    asm("mma.sync.aligned.m16n8k8.row.col.f32.f16.f16.f32 "
        "{%0,%1,%2,%3},{%4,%5},{%6},{%0,%1,%2,%3};"
        : "+f"(c0), "+f"(c1), "+f"(c2), "+f"(c3)
        : "r"(a0), "r"(a1), "r"(b0));
}

__device__ __forceinline__ void red2(float* p, float a, float b) {
    asm volatile("red.global.add.v2.f32 [%0], {%1, %2};"
                 :: "l"(p), "f"(a), "f"(b) : "memory");
}

__device__ __forceinline__ int ld_src(const void* ei, int e) {
    return g_is64 ? (int)((const long long*)ei)[e] : ((const int*)ei)[e];
}
__device__ __forceinline__ int ld_dst(const void* ei, int e) {
    return g_is64 ? (int)((const long long*)ei)[EE + e] : ((const int*)ei)[EE + e];
}

// ---------------- build kernels ----------------

// Zero counters; block0/warp0 probes dtype (int64 vs JAX-x64-disabled int32).
__global__ void __launch_bounds__(256) zero_detect_kernel(const void* ei) {
    if (blockIdx.x == 0 && threadIdx.x < 32) {
        const unsigned long long* p = (const unsigned long long*)ei;
        int t = threadIdx.x;
        bool bad = (p[t] >= (unsigned long long)NN) ||
                   (p[t + 32] >= (unsigned long long)NN);
        unsigned m = __ballot_sync(0xffffffffu, bad);
        if (t == 0) g_is64 = (m == 0) ? 1 : 0;
    }
    int idx = blockIdx.x * blockDim.x + threadIdx.x;
    int stride = gridDim.x * blockDim.x;
    for (int i = idx; i < NN; i += stride) {
        g_cnts[i] = 0;
        g_cursor[i] = 0;
        g_cnt[i] = 0.f;
    }
}

// src out-degree + dst in-degree histograms.
__global__ void __launch_bounds__(256) hist_kernel(const void* __restrict__ ei) {
    int e = blockIdx.x * blockDim.x + threadIdx.x;
    if (e >= EE) return;
    int src = ld_src(ei, e);
    int dst = ld_dst(ei, e);
    if ((unsigned)src < NN) atomicAdd(&g_cnts[src], 1);
    if ((unsigned)dst < NN) atomicAdd(&g_cnt[dst], 1.0f);
}

// Scan phase 1: per-block sums of 16-padded counts.
__global__ void __launch_bounds__(256) scan1_kernel() {
    __shared__ int sh[256];
    int n = blockIdx.x * 256 + threadIdx.x;
    int pc = (n < NN) ? ((g_cnts[n] + 15) & ~15) : 0;
    sh[threadIdx.x] = pc;
    __syncthreads();
    for (int d = 128; d > 0; d >>= 1) {
        if (threadIdx.x < d) sh[threadIdx.x] += sh[threadIdx.x + d];
        __syncthreads();
    }
    if (threadIdx.x == 0) g_bsum[blockIdx.x] = sh[0];
}

// Scan phase 2: scan NB1 block sums; total -> g_off[NN].
__global__ void __launch_bounds__(256) scan2_kernel() {
    __shared__ int sh[256];
    int t = threadIdx.x;
    int v = (t < NB1) ? g_bsum[t] : 0;
    int incl = v;
    for (int d = 1; d < 256; d <<= 1) {
        sh[t] = incl;
        __syncthreads();
        if (t >= d) incl += sh[t - d];
        __syncthreads();
    }
    if (t < NB1) g_bpre[t] = incl - v;
    if (t == NB1 - 1) g_off[NN] = incl;
}

// Scan phase 3: final padded offsets; fill pad slots' {src,dst} with {0, NN}.
__global__ void __launch_bounds__(256) scan3_kernel() {
    __shared__ int sh[256];
    int t = threadIdx.x;
    int n = blockIdx.x * 256 + t;
    int cnt = (n < NN) ? g_cnts[n] : 0;
    int pc = (cnt + 15) & ~15;
    int incl = pc;
    for (int d = 1; d < 256; d <<= 1) {
        sh[t] = incl;
        __syncthreads();
        if (t >= d) incl += sh[t - d];
        __syncthreads();
    }
    if (n < NN) {
        int off = g_bpre[blockIdx.x] + incl - pc;
        g_off[n] = off;
        for (int j = cnt; j < pc; j++)
            g_sdS[off + j] = make_int2(0, NN);
    }
}

// Scatter edges into src-grouped padded slots; ea converted to fp16 inline.
__global__ void __launch_bounds__(256) scatter_kernel(const void* __restrict__ ei,
                                                      const float* __restrict__ ea) {
    int e = blockIdx.x * blockDim.x + threadIdx.x;
    if (e >= EE) return;
    int src = ld_src(ei, e);
    int dst = ld_dst(ei, e);
    if ((unsigned)src >= NN) return;
    if ((unsigned)dst >= NN) dst = NN;       // guarded out at scatter time
    int p = g_off[src] + atomicAdd(&g_cursor[src], 1);
    g_sdS[p] = make_int2(src, dst);
    const float4* ep = (const float4*)(ea + (size_t)e * 8);
    float4 u = ep[0], v = ep[1];
    __half2 h0 = __floats2half2_rn(u.x, u.y);
    __half2 h1 = __floats2half2_rn(u.z, u.w);
    __half2 h2 = __floats2half2_rn(v.x, v.y);
    __half2 h3 = __floats2half2_rn(v.z, v.w);
    unsigned w0 = *(unsigned*)&h0;
    unsigned w1 = *(unsigned*)&h1;
    unsigned w2 = *(unsigned*)&h2;
    unsigned w3 = *(unsigned*)&h3;
    *(uint4*)(g_eaS + (size_t)p * 8) = make_uint4(w0, w1, w2, w3);
}

// ---------------- node prep (tf32 MMA core) ----------------
// mode 0: input = x; zeroes agg0. mode 1: input = relu(agg0/cnt+rootx) inline; zeroes agg1.
__global__ void __launch_bounds__(256)
node_prep_kernel(const float* __restrict__ xin,
                 const float* __restrict__ nw,
                 const float* __restrict__ nb,
                 const float* __restrict__ rt,
                 const float* __restrict__ bs,
                 int mode) {
    __shared__ unsigned Wt[16 * WSTRIDE];
    __shared__ float    Bs[16];
    __shared__ __half   stage[8][16 * SSTRIDE];

    {
        int idx = blockIdx.x * blockDim.x + threadIdx.x;
        int stride = gridDim.x * blockDim.x;
        float4 z4 = make_float4(0.f, 0.f, 0.f, 0.f);
        float4* aggv = (float4*)(mode == 0 ? g_agg0 : g_agg1);
        for (int i = idx; i < (NN + 1) * 4; i += stride) aggv[i] = z4;
    }

    for (int t = threadIdx.x; t < 16 * 160; t += blockDim.x) {
        int i = t / 160, j = t % 160;
        float w;
        if (j < 128) {
            int d = j >> 4, o = j & 15;
            w = nw[d * 256 + i * 16 + o];
        } else if (j < 144) {
            w = nb[i * 16 + (j - 128)];
        } else {
            w = rt[i * 16 + (j - 144)];
        }
        Wt[i * WSTRIDE + j] = tf32_of(w);
    }
    if (threadIdx.x < 16) Bs[threadIdx.x] = bs[threadIdx.x];
    __syncthreads();

    int wid = threadIdx.x >> 5;
    int lane = threadIdx.x & 31;
    int g = lane >> 2;
    int t4 = lane & 3;

    int m = blockIdx.x * 8 + wid;
    if (m >= MT) return;
    int base = m * 16;

    unsigned A[2][4];
    if (mode == 0) {
        const float* x0 = xin + (size_t)(base + g) * 16;
        const float* x1 = xin + (size_t)(base + g + 8) * 16;
#pragma unroll
        for (int kh = 0; kh < 2; kh++) {
            A[kh][0] = tf32_of(x0[kh * 8 + t4]);
            A[kh][1] = tf32_of(x1[kh * 8 + t4]);
            A[kh][2] = tf32_of(x0[kh * 8 + t4 + 4]);
            A[kh][3] = tf32_of(x1[kh * 8 + t4 + 4]);
        }
    } else {
        int r0 = base + g, r1 = base + g + 8;
        float inv0 = 1.f / fmaxf(g_cnt[r0], 1.f);
        float inv1 = 1.f / fmaxf(g_cnt[r1], 1.f);
        const float* a0p = g_agg0 + (size_t)r0 * 16;
        const float* a1p = g_agg0 + (size_t)r1 * 16;
        const float* x0p = g_rootx + (size_t)r0 * 16;
        const float* x1p = g_rootx + (size_t)r1 * 16;
#pragma unroll
        for (int kh = 0; kh < 2; kh++) {
            int k = kh * 8 + t4;
            A[kh][0] = tf32_of(fmaxf(fmaf(a0p[k], inv0, x0p[k]), 0.f));
            A[kh][1] = tf32_of(fmaxf(fmaf(a1p[k], inv1, x1p[k]), 0.f));
            A[kh][2] = tf32_of(fmaxf(fmaf(a0p[k + 4], inv0, x0p[k + 4]), 0.f));
            A[kh][3] = tf32_of(fmaxf(fmaf(a1p[k + 4], inv1, x1p[k + 4]), 0.f));
        }
    }

    __half* st = stage[wid];

#pragma unroll
    for (int nbt = 0; nbt < 20; nbt++) {
        float c0 = 0.f, c1 = 0.f, c2 = 0.f, c3 = 0.f;
#pragma unroll
        for (int kh = 0; kh < 2; kh++) {
            unsigned b0 = Wt[(kh * 8 + t4) * WSTRIDE + nbt * 8 + g];
            unsigned b1 = Wt[(kh * 8 + t4 + 4) * WSTRIDE + nbt * 8 + g];
            mma_tf32(c0, c1, c2, c3, A[kh][0], A[kh][1], A[kh][2], A[kh][3], b0, b1);
        }
        if (nbt < 16) {
            int d = nbt >> 1;
            int o0 = (nbt & 1) * 8 + 2 * t4;
            int idx0 = (o0 >> 1) * 8 + d;
            st[g * SSTRIDE + idx0]            = __float2half_rn(c0);
            st[g * SSTRIDE + idx0 + 64]       = __float2half_rn(c1);
            st[(g + 8) * SSTRIDE + idx0]      = __float2half_rn(c2);
            st[(g + 8) * SSTRIDE + idx0 + 64] = __float2half_rn(c3);
        } else if (nbt < 18) {
            int o0 = (nbt - 16) * 8 + 2 * t4;
            *(float2*)&g_xb[(size_t)(base + g) * 16 + o0]     = make_float2(c0, c1);
            *(float2*)&g_xb[(size_t)(base + g + 8) * 16 + o0] = make_float2(c2, c3);
        } else {
            int o0 = (nbt - 18) * 8 + 2 * t4;
            float b0v = Bs[o0], b1v = Bs[o0 + 1];
            *(float2*)&g_rootx[(size_t)(base + g) * 16 + o0]     = make_float2(c0 + b0v, c1 + b1v);
            *(float2*)&g_rootx[(size_t)(base + g + 8) * 16 + o0] = make_float2(c2 + b0v, c3 + b1v);
        }
    }
    __syncwarp();

    for (int it = lane; it < 256; it += 32) {
        int r = it >> 4;
        int q = it & 15;
        float4 v = *(const float4*)(st + r * SSTRIDE + q * 8);
        *(float4*)((char*)(g_TextH + (size_t)(base + r) * ROWH) + q * 16) = v;
    }
}

// ---------------- edge MMA kernel ----------------
// Warp handles one 16-slot tile (single src): C[16,16] = EA[16,8] @ T_src[8,16]
// via two mma.m16n8k8.f16.f32, then adds xb[src] and red2-scatters to dst rows.
// Pad slots (dst==NN) are PREDICATED OUT of the scatter -- the R15 dump-row
// same-address red storm was the entire 19x regression.
__global__ void __launch_bounds__(256)
edge_mma_kernel(int layer) {
    int wtile = blockIdx.x * 8 + (threadIdx.x >> 5);
    int tot = g_off[NN];
    if (wtile * 16 >= tot) return;
    int lane = threadIdx.x & 31;
    int g = lane >> 2;
    int t4 = lane & 3;
    int base = wtile * 16;

    int src = g_sdS[base].x;                    // whole warp: same addr (broadcast)

    // A fragments: rows g, g+8 of EA (16 rows x 8 halves = 16B/row)
    const __half* eaRow = g_eaS + (size_t)(base + g) * 8;
    unsigned a0 = *(const unsigned*)(eaRow + 2 * t4);
    unsigned a1 = *(const unsigned*)(eaRow + 64 + 2 * t4);   // row g+8

    // B fragments from fp16 T row (o-major permuted): col c at halves
    //   (c even) 8*(c/2)  |  (c odd) 64 + 8*(c/2);  lane takes d = 2t4, 2t4+1.
    const __half* trow = g_TextH + (size_t)src * ROWH;
    int cb0 = ((g & 1) ? 64 + 8 * (g >> 1) : 8 * (g >> 1)) + 2 * t4;
    int c1i = 8 + g;
    int cb1 = ((c1i & 1) ? 64 + 8 * (c1i >> 1) : 8 * (c1i >> 1)) + 2 * t4;
    unsigned b0 = *(const unsigned*)(trow + cb0);
    unsigned b1 = *(const unsigned*)(trow + cb1);

    float c00 = 0.f, c01 = 0.f, c02 = 0.f, c03 = 0.f;
    float c10 = 0.f, c11 = 0.f, c12 = 0.f, c13 = 0.f;
    mma_f16(c00, c01, c02, c03, a0, a1, b0);   // cols 0..7 (ntile0)
    mma_f16(c10, c11, c12, c13, a0, a1, b1);   // cols 8..15 (ntile1)

    float2 xbA = *(const float2*)(g_xb + (size_t)src * 16 + 2 * t4);
    float2 xbB = *(const float2*)(g_xb + (size_t)src * 16 + 8 + 2 * t4);

    int dlo = g_sdS[base + g].y;
    int dhi = g_sdS[base + g + 8].y;

    float* agg = layer ? g_agg1 : g_agg0;
    if (dlo < NN) {
        red2(agg + (size_t)dlo * 16 + 2 * t4,     c00 + xbA.x, c01 + xbA.y);
        red2(agg + (size_t)dlo * 16 + 8 + 2 * t4, c10 + xbB.x, c11 + xbB.y);
    }
    if (dhi < NN) {
        red2(agg + (size_t)dhi * 16 + 2 * t4,     c02 + xbA.x, c03 + xbA.y);
        red2(agg + (size_t)dhi * 16 + 8 + 2 * t4, c12 + xbB.x, c13 + xbB.y);
    }
}

// out[n] = sum_o relu(agg1[n,o]/max(cnt,1) + rootx[n,o]) * head_w[o] + head_b
__global__ void __launch_bounds__(256)
head_kernel(const float* __restrict__ hw,
            const float* __restrict__ hb,
            float* __restrict__ out) {
    int n = blockIdx.x * blockDim.x + threadIdx.x;
    if (n >= NN) return;
    float inv = 1.f / fmaxf(g_cnt[n], 1.f);
    const float4* ag = (const float4*)(g_agg1 + (size_t)n * 16);
    const float4* rx = (const float4*)(g_rootx + (size_t)n * 16);
    float s = hb[0];
#pragma unroll
    for (int q = 0; q < 4; q++) {
        float4 a = ag[q], r = rx[q];
        const float4 w = ((const float4*)hw)[q];
        s = fmaf(fmaxf(fmaf(a.x, inv, r.x), 0.f), w.x, s);
        s = fmaf(fmaxf(fmaf(a.y, inv, r.y), 0.f), w.y, s);
        s = fmaf(fmaxf(fmaf(a.z, inv, r.z), 0.f), w.z, s);
        s = fmaf(fmaxf(fmaf(a.w, inv, r.w), 0.f), w.w, s);
    }
    out[n] = s;
}

// ---------------- launch ----------------
extern "C" void kernel_launch(void* const* d_in, const int* in_sizes, int n_in,
                              void* d_out, int out_size) {
    const float* x     = (const float*)d_in[0];
    const void*  ei    = d_in[1];
    const float* ea    = (const float*)d_in[2];
    const float* nn_w0 = (const float*)d_in[3];
    const float* nn_b0 = (const float*)d_in[4];
    const float* root0 = (const float*)d_in[5];
    const float* bias0 = (const float*)d_in[6];
    const float* nn_w1 = (const float*)d_in[7];
    const float* nn_b1 = (const float*)d_in[8];
    const float* root1 = (const float*)d_in[9];
    const float* bias1 = (const float*)d_in[10];
    const float* headw = (const float*)d_in[11];
    const float* headb = (const float*)d_in[12];
    float* out = (float*)d_out;

    const int TB = 256;
    const int EB = EE / TB;               // 3125, exact
    const int PB = (MT + 7) / 8;          // 391
    const int MB = TILECAP / 8;           // 12500 blocks, 8 warp-tiles each

    zero_detect_kernel<<<256, TB>>>(ei);
    hist_kernel<<<EB, TB>>>(ei);
    scan1_kernel<<<NB1, TB>>>();
    scan2_kernel<<<1, TB>>>();
    scan3_kernel<<<NB1, TB>>>();
    scatter_kernel<<<EB, TB>>>(ei, ea);
    node_prep_kernel<<<PB, TB>>>(x, nn_w0, nn_b0, root0, bias0, /*mode=*/0);
    edge_mma_kernel<<<MB, TB>>>(/*layer=*/0);
    node_prep_kernel<<<PB, TB>>>(nullptr, nn_w1, nn_b1, root1, bias1, /*mode=*/1);
    edge_mma_kernel<<<MB, TB>>>(/*layer=*/1);
    head_kernel<<<(NN + TB - 1) / TB, TB>>>(headw, headb, out);
}

// round 17
// speedup vs baseline: 14.7477x; 1.0209x over previous
#include <cuda_runtime.h>
#include <cuda_fp16.h>

// Problem constants
#define NN    50000
#define EE    800000
#define ROWH  128       // fp16 T-table stride in halves
#define MT    3125      // 16-node m-tiles for node prep
#define WSTRIDE 168
#define SSTRIDE 136
#define SLOTCAP (EE + 16 * NN)        // 1.6M padded edge slots (upper bound)
#define TILECAP (SLOTCAP / 16)        // 100000 warp tiles
#define NB1   196                     // ceil(NN/256) scan blocks

// ---------------- scratch (static device memory; no runtime allocation) ----------------
__device__ __half g_TextH[(size_t)NN * ROWH];     // 12.8 MB
__device__ float  g_xb[NN * 16];
__device__ float  g_rootx[NN * 16];
__device__ float  g_agg0[(NN + 1) * 16];
__device__ float  g_agg1[(NN + 1) * 16];
__device__ float  g_cnt[NN];                      // dst in-degree (float); zeroed in head tail
__device__ int    g_cnts[NN];                     // src out-degree; zeroed in head tail
__device__ int    g_cursor[NN];                   // zeroed in head tail
__device__ int    g_off[NN + 2];
__device__ int    g_bsum[NB1];
__device__ __half g_eaS[(size_t)SLOTCAP * 8];     // slot-ordered fp16 edge attrs (pads stay 0)
__device__ int2   g_sdS[SLOTCAP];                 // {src, dst} per slot; pads {0, NN}
__device__ int    g_is64;

// ---------------- helpers ----------------
__device__ __forceinline__ unsigned tf32_of(float f) {
    unsigned r;
    asm("cvt.rna.tf32.f32 %0, %1;" : "=r"(r) : "f"(f));
    return r;
}

__device__ __forceinline__ void mma_tf32(float& c0, float& c1, float& c2, float& c3,
                                         unsigned a0, unsigned a1, unsigned a2, unsigned a3,
                                         unsigned b0, unsigned b1) {
    asm("mma.sync.aligned.m16n8k8.row.col.f32.tf32.tf32.f32 "
        "{%0,%1,%2,%3},{%4,%5,%6,%7},{%8,%9},{%0,%1,%2,%3};"
        : "+f"(c0), "+f"(c1), "+f"(c2), "+f"(c3)
        : "r"(a0), "r"(a1), "r"(a2), "r"(a3), "r"(b0), "r"(b1));
}

__device__ __forceinline__ void mma_f16(float& c0, float& c1, float& c2, float& c3,
                                        unsigned a0, unsigned a1, unsigned b0) {
    asm("mma.sync.aligned.m16n8k8.row.col.f32.f16.f16.f32 "
        "{%0,%1,%2,%3},{%4,%5},{%6},{%0,%1,%2,%3};"
        : "+f"(c0), "+f"(c1), "+f"(c2), "+f"(c3)
        : "r"(a0), "r"(a1), "r"(b0));
}

__device__ __forceinline__ void red2(float* p, float a, float b) {
    asm volatile("red.global.add.v2.f32 [%0], {%1, %2};"
                 :: "l"(p), "f"(a), "f"(b) : "memory");
}

__device__ __forceinline__ int ld_src(const void* ei, int e) {
    return g_is64 ? (int)((const long long*)ei)[e] : ((const int*)ei)[e];
}
__device__ __forceinline__ int ld_dst(const void* ei, int e) {
    return g_is64 ? (int)((const long long*)ei)[EE + e] : ((const int*)ei)[EE + e];
}

// ---------------- build kernels ----------------

// src out-degree + dst in-degree histograms (counters pre-zeroed by head tail / BSS).
__global__ void __launch_bounds__(256) hist_kernel(const void* __restrict__ ei) {
    int e = blockIdx.x * blockDim.x + threadIdx.x;
    if (e >= EE) return;
    int src = ld_src(ei, e);
    int dst = ld_dst(ei, e);
    if ((unsigned)src < NN) atomicAdd(&g_cnts[src], 1);
    if ((unsigned)dst < NN) atomicAdd(&g_cnt[dst], 1.0f);
}

// Scan phase 1: per-block sums of 16-padded counts.
__global__ void __launch_bounds__(256) scan1_kernel() {
    __shared__ int sh[256];
    int n = blockIdx.x * 256 + threadIdx.x;
    int pc = (n < NN) ? ((g_cnts[n] + 15) & ~15) : 0;
    sh[threadIdx.x] = pc;
    __syncthreads();
    for (int d = 128; d > 0; d >>= 1) {
        if (threadIdx.x < d) sh[threadIdx.x] += sh[threadIdx.x + d];
        __syncthreads();
    }
    if (threadIdx.x == 0) g_bsum[blockIdx.x] = sh[0];
}

// Scan phase 2 (fused): every block scans the NB1 block sums itself (cheap),
// then produces final padded offsets and fills pad slots' {src,dst} with {0, NN}.
__global__ void __launch_bounds__(256) scan3_kernel() {
    __shared__ int sh[256];
    int t = threadIdx.x;

    // scan the 196 block sums
    int v = (t < NB1) ? g_bsum[t] : 0;
    int incl = v;
    for (int d = 1; d < 256; d <<= 1) {
        sh[t] = incl;
        __syncthreads();
        if (t >= d) incl += sh[t - d];
        __syncthreads();
    }
    sh[t] = incl;
    __syncthreads();
    int bpre = (blockIdx.x > 0) ? sh[blockIdx.x - 1] : 0;
    int total = sh[NB1 - 1];
    __syncthreads();   // before reusing sh
    if (blockIdx.x == 0 && t == 0) g_off[NN] = total;

    // per-node scan within this block
    int n = blockIdx.x * 256 + t;
    int cnt = (n < NN) ? g_cnts[n] : 0;
    int pc = (cnt + 15) & ~15;
    int incl2 = pc;
    for (int d = 1; d < 256; d <<= 1) {
        sh[t] = incl2;
        __syncthreads();
        if (t >= d) incl2 += sh[t - d];
        __syncthreads();
    }
    if (n < NN) {
        int off = bpre + incl2 - pc;
        g_off[n] = off;
        for (int j = cnt; j < pc; j++)
            g_sdS[off + j] = make_int2(0, NN);
    }
}

// Scatter edges into src-grouped padded slots; ea converted to fp16 inline.
__global__ void __launch_bounds__(256) scatter_kernel(const void* __restrict__ ei,
                                                      const float* __restrict__ ea) {
    int e = blockIdx.x * blockDim.x + threadIdx.x;
    if (e >= EE) return;
    int src = ld_src(ei, e);
    int dst = ld_dst(ei, e);
    if ((unsigned)src >= NN) return;
    if ((unsigned)dst >= NN) dst = NN;
    int p = g_off[src] + atomicAdd(&g_cursor[src], 1);
    g_sdS[p] = make_int2(src, dst);
    const float4* ep = (const float4*)(ea + (size_t)e * 8);
    float4 u = ep[0], v = ep[1];
    __half2 h0 = __floats2half2_rn(u.x, u.y);
    __half2 h1 = __floats2half2_rn(u.z, u.w);
    __half2 h2 = __floats2half2_rn(v.x, v.y);
    __half2 h3 = __floats2half2_rn(v.z, v.w);
    unsigned w0 = *(unsigned*)&h0;
    unsigned w1 = *(unsigned*)&h1;
    unsigned w2 = *(unsigned*)&h2;
    unsigned w3 = *(unsigned*)&h3;
    *(uint4*)(g_eaS + (size_t)p * 8) = make_uint4(w0, w1, w2, w3);
}

// ---------------- node prep (tf32 MMA core) ----------------
// mode 0: input = x; zeroes agg0; block0/warp0 probes dtype (hist runs later).
// mode 1: input = relu(agg0/cnt+rootx) inline; zeroes agg1.
__global__ void __launch_bounds__(256)
node_prep_kernel(const float* __restrict__ xin,
                 const float* __restrict__ nw,
                 const float* __restrict__ nb,
                 const float* __restrict__ rt,
                 const float* __restrict__ bs,
                 const void* __restrict__ ei,
                 int mode) {
    __shared__ unsigned Wt[16 * WSTRIDE];
    __shared__ float    Bs[16];
    __shared__ __half   stage[8][16 * SSTRIDE];

    if (mode == 0 && blockIdx.x == 0 && threadIdx.x < 32) {
        const unsigned long long* p = (const unsigned long long*)ei;
        int t = threadIdx.x;
        bool bad = (p[t] >= (unsigned long long)NN) ||
                   (p[t + 32] >= (unsigned long long)NN);
        unsigned m = __ballot_sync(0xffffffffu, bad);
        if (t == 0) g_is64 = (m == 0) ? 1 : 0;
    }
    {
        int idx = blockIdx.x * blockDim.x + threadIdx.x;
        int stride = gridDim.x * blockDim.x;
        float4 z4 = make_float4(0.f, 0.f, 0.f, 0.f);
        float4* aggv = (float4*)(mode == 0 ? g_agg0 : g_agg1);
        for (int i = idx; i < (NN + 1) * 4; i += stride) aggv[i] = z4;
    }

    for (int t = threadIdx.x; t < 16 * 160; t += blockDim.x) {
        int i = t / 160, j = t % 160;
        float w;
        if (j < 128) {
            int d = j >> 4, o = j & 15;
            w = nw[d * 256 + i * 16 + o];
        } else if (j < 144) {
            w = nb[i * 16 + (j - 128)];
        } else {
            w = rt[i * 16 + (j - 144)];
        }
        Wt[i * WSTRIDE + j] = tf32_of(w);
    }
    if (threadIdx.x < 16) Bs[threadIdx.x] = bs[threadIdx.x];
    __syncthreads();

    int wid = threadIdx.x >> 5;
    int lane = threadIdx.x & 31;
    int g = lane >> 2;
    int t4 = lane & 3;

    int m = blockIdx.x * 8 + wid;
    if (m >= MT) return;
    int base = m * 16;

    unsigned A[2][4];
    if (mode == 0) {
        const float* x0 = xin + (size_t)(base + g) * 16;
        const float* x1 = xin + (size_t)(base + g + 8) * 16;
#pragma unroll
        for (int kh = 0; kh < 2; kh++) {
            A[kh][0] = tf32_of(x0[kh * 8 + t4]);
            A[kh][1] = tf32_of(x1[kh * 8 + t4]);
            A[kh][2] = tf32_of(x0[kh * 8 + t4 + 4]);
            A[kh][3] = tf32_of(x1[kh * 8 + t4 + 4]);
        }
    } else {
        int r0 = base + g, r1 = base + g + 8;
        float inv0 = 1.f / fmaxf(g_cnt[r0], 1.f);
        float inv1 = 1.f / fmaxf(g_cnt[r1], 1.f);
        const float* a0p = g_agg0 + (size_t)r0 * 16;
        const float* a1p = g_agg0 + (size_t)r1 * 16;
        const float* x0p = g_rootx + (size_t)r0 * 16;
        const float* x1p = g_rootx + (size_t)r1 * 16;
#pragma unroll
        for (int kh = 0; kh < 2; kh++) {
            int k = kh * 8 + t4;
            A[kh][0] = tf32_of(fmaxf(fmaf(a0p[k], inv0, x0p[k]), 0.f));
            A[kh][1] = tf32_of(fmaxf(fmaf(a1p[k], inv1, x1p[k]), 0.f));
            A[kh][2] = tf32_of(fmaxf(fmaf(a0p[k + 4], inv0, x0p[k + 4]), 0.f));
            A[kh][3] = tf32_of(fmaxf(fmaf(a1p[k + 4], inv1, x1p[k + 4]), 0.f));
        }
    }

    __half* st = stage[wid];

#pragma unroll
    for (int nbt = 0; nbt < 20; nbt++) {
        float c0 = 0.f, c1 = 0.f, c2 = 0.f, c3 = 0.f;
#pragma unroll
        for (int kh = 0; kh < 2; kh++) {
            unsigned b0 = Wt[(kh * 8 + t4) * WSTRIDE + nbt * 8 + g];
            unsigned b1 = Wt[(kh * 8 + t4 + 4) * WSTRIDE + nbt * 8 + g];
            mma_tf32(c0, c1, c2, c3, A[kh][0], A[kh][1], A[kh][2], A[kh][3], b0, b1);
        }
        if (nbt < 16) {
            int d = nbt >> 1;
            int o0 = (nbt & 1) * 8 + 2 * t4;
            int idx0 = (o0 >> 1) * 8 + d;
            st[g * SSTRIDE + idx0]            = __float2half_rn(c0);
            st[g * SSTRIDE + idx0 + 64]       = __float2half_rn(c1);
            st[(g + 8) * SSTRIDE + idx0]      = __float2half_rn(c2);
            st[(g + 8) * SSTRIDE + idx0 + 64] = __float2half_rn(c3);
        } else if (nbt < 18) {
            int o0 = (nbt - 16) * 8 + 2 * t4;
            *(float2*)&g_xb[(size_t)(base + g) * 16 + o0]     = make_float2(c0, c1);
            *(float2*)&g_xb[(size_t)(base + g + 8) * 16 + o0] = make_float2(c2, c3);
        } else {
            int o0 = (nbt - 18) * 8 + 2 * t4;
            float b0v = Bs[o0], b1v = Bs[o0 + 1];
            *(float2*)&g_rootx[(size_t)(base + g) * 16 + o0]     = make_float2(c0 + b0v, c1 + b1v);
            *(float2*)&g_rootx[(size_t)(base + g + 8) * 16 + o0] = make_float2(c2 + b0v, c3 + b1v);
        }
    }
    __syncwarp();

    for (int it = lane; it < 256; it += 32) {
        int r = it >> 4;
        int q = it & 15;
        float4 v = *(const float4*)(st + r * SSTRIDE + q * 8);
        *(float4*)((char*)(g_TextH + (size_t)(base + r) * ROWH) + q * 16) = v;
    }
}

// ---------------- edge MMA kernel ----------------
// Warp = one 16-slot tile (single src): C[16,16] = EA[16,8] @ T_src[8,16]
// via two mma.m16n8k8.f16.f32; adds xb[src]; predicated red2 scatter to dst rows.
__global__ void __launch_bounds__(256)
edge_mma_kernel(int layer) {
    int wtile = blockIdx.x * 8 + (threadIdx.x >> 5);
    int tot = g_off[NN];
    if (wtile * 16 >= tot) return;
    int lane = threadIdx.x & 31;
    int g = lane >> 2;
    int t4 = lane & 3;
    int base = wtile * 16;

    int src = g_sdS[base].x;

    const __half* eaRow = g_eaS + (size_t)(base + g) * 8;
    unsigned a0 = *(const unsigned*)(eaRow + 2 * t4);
    unsigned a1 = *(const unsigned*)(eaRow + 64 + 2 * t4);

    const __half* trow = g_TextH + (size_t)src * ROWH;
    int cb0 = ((g & 1) ? 64 + 8 * (g >> 1) : 8 * (g >> 1)) + 2 * t4;
    int c1i = 8 + g;
    int cb1 = ((c1i & 1) ? 64 + 8 * (c1i >> 1) : 8 * (c1i >> 1)) + 2 * t4;
    unsigned b0 = *(const unsigned*)(trow + cb0);
    unsigned b1 = *(const unsigned*)(trow + cb1);

    float c00 = 0.f, c01 = 0.f, c02 = 0.f, c03 = 0.f;
    float c10 = 0.f, c11 = 0.f, c12 = 0.f, c13 = 0.f;
    mma_f16(c00, c01, c02, c03, a0, a1, b0);
    mma_f16(c10, c11, c12, c13, a0, a1, b1);

    float2 xbA = *(const float2*)(g_xb + (size_t)src * 16 + 2 * t4);
    float2 xbB = *(const float2*)(g_xb + (size_t)src * 16 + 8 + 2 * t4);

    int dlo = g_sdS[base + g].y;
    int dhi = g_sdS[base + g + 8].y;

    float* agg = layer ? g_agg1 : g_agg0;
    if (dlo < NN) {
        red2(agg + (size_t)dlo * 16 + 2 * t4,     c00 + xbA.x, c01 + xbA.y);
        red2(agg + (size_t)dlo * 16 + 8 + 2 * t4, c10 + xbB.x, c11 + xbB.y);
    }
    if (dhi < NN) {
        red2(agg + (size_t)dhi * 16 + 2 * t4,     c02 + xbA.x, c03 + xbA.y);
        red2(agg + (size_t)dhi * 16 + 8 + 2 * t4, c12 + xbB.x, c13 + xbB.y);
    }
}

// out[n] = sum_o relu(agg1[n,o]/max(cnt,1) + rootx[n,o]) * head_w[o] + head_b
// Tail: zero counters for the NEXT graph replay (first call relies on BSS zeros).
__global__ void __launch_bounds__(256)
head_kernel(const float* __restrict__ hw,
            const float* __restrict__ hb,
            float* __restrict__ out) {
    int n = blockIdx.x * blockDim.x + threadIdx.x;
    if (n >= NN) return;
    float inv = 1.f / fmaxf(g_cnt[n], 1.f);
    const float4* ag = (const float4*)(g_agg1 + (size_t)n * 16);
    const float4* rx = (const float4*)(g_rootx + (size_t)n * 16);
    float s = hb[0];
#pragma unroll
    for (int q = 0; q < 4; q++) {
        float4 a = ag[q], r = rx[q];
        const float4 w = ((const float4*)hw)[q];
        s = fmaf(fmaxf(fmaf(a.x, inv, r.x), 0.f), w.x, s);
        s = fmaf(fmaxf(fmaf(a.y, inv, r.y), 0.f), w.y, s);
        s = fmaf(fmaxf(fmaf(a.z, inv, r.z), 0.f), w.z, s);
        s = fmaf(fmaxf(fmaf(a.w, inv, r.w), 0.f), w.w, s);
    }
    out[n] = s;
    // reset counters for the next replay
    g_cnt[n] = 0.f;
    g_cnts[n] = 0;
    g_cursor[n] = 0;
}

// ---------------- launch ----------------
extern "C" void kernel_launch(void* const* d_in, const int* in_sizes, int n_in,
                              void* d_out, int out_size) {
    const float* x     = (const float*)d_in[0];
    const void*  ei    = d_in[1];
    const float* ea    = (const float*)d_in[2];
    const float* nn_w0 = (const float*)d_in[3];
    const float* nn_b0 = (const float*)d_in[4];
    const float* root0 = (const float*)d_in[5];
    const float* bias0 = (const float*)d_in[6];
    const float* nn_w1 = (const float*)d_in[7];
    const float* nn_b1 = (const float*)d_in[8];
    const float* root1 = (const float*)d_in[9];
    const float* bias1 = (const float*)d_in[10];
    const float* headw = (const float*)d_in[11];
    const float* headb = (const float*)d_in[12];
    float* out = (float*)d_out;

    const int TB = 256;
    const int EB = EE / TB;               // 3125, exact
    const int PB = (MT + 7) / 8;          // 391
    const int MB = TILECAP / 8;           // 12500

    // Order chosen so edge_mma layer-0 is the 6th launch (ncu -s 5 -c 1 profiles it).
    node_prep_kernel<<<PB, TB>>>(x, nn_w0, nn_b0, root0, bias0, ei, /*mode=*/0);  // 1
    hist_kernel<<<EB, TB>>>(ei);                                                  // 2
    scan1_kernel<<<NB1, TB>>>();                                                  // 3
    scan3_kernel<<<NB1, TB>>>();                                                  // 4
    scatter_kernel<<<EB, TB>>>(ei, ea);                                           // 5
    edge_mma_kernel<<<MB, TB>>>(/*layer=*/0);                                     // 6 <- profiled
    node_prep_kernel<<<PB, TB>>>(nullptr, nn_w1, nn_b1, root1, bias1, ei, 1);     // 7
    edge_mma_kernel<<<MB, TB>>>(/*layer=*/1);                                     // 8
    head_kernel<<<(NN + TB - 1) / TB, TB>>>(headw, headb, out);                   // 9
}